// round 5
// baseline (speedup 1.0000x reference)
#include <cuda_runtime.h>
#include <cstdint>

#define BB 64
#define MM 2048
#define DD 512
#define TOTAL_ROWS (BB * MM)            // 131072
#define GRID_BLOCKS (148 * 4)           // 592
#define WARPS_TOTAL (GRID_BLOCKS * 8)   // 4736

// Per-batch best: high 32 = float bits of squared distance (non-negative ->
// monotone bit pattern), low 32 = (MM-1-idx) so ties pick the SMALLEST index
// under atomicMax (matches jnp.argmax first-occurrence). Zero-init at load;
// the finishing warp resets it after the gather so graph replays stay clean.
__device__ unsigned long long g_best[BB];
__device__ int g_cnt[BB];

__device__ __forceinline__ void flush_batch(
    int b, float best, int bestm, int nrows, int lane,
    const float* __restrict__ buffer, float* __restrict__ out)
{
    unsigned long long packed =
        ((unsigned long long)__float_as_uint(best) << 32) |
        (unsigned int)(MM - 1 - bestm);
    int fin = 0;
    if (lane == 0) {
        atomicMax(&g_best[b], packed);
        __threadfence();                       // max visible before count
        int old = atomicAdd(&g_cnt[b], nrows);
        fin = (old + nrows == MM);
    }
    fin = __shfl_sync(0xFFFFFFFFu, fin, 0);
    if (fin) {
        unsigned long long win = 0ULL;
        if (lane == 0) {
            __threadfence();                   // acquire all maxes
            win = g_best[b];
        }
        win = __shfl_sync(0xFFFFFFFFu, win, 0);
        const int idx = MM - 1 - (int)(unsigned int)(win & 0xFFFFFFFFu);
        const float4* src = reinterpret_cast<const float4*>(
            buffer + ((size_t)b * MM + (size_t)idx) * DD);
        float4* dst = reinterpret_cast<float4*>(out + (size_t)b * DD);
#pragma unroll
        for (int i = 0; i < 4; i++)
            dst[lane + i * 32] = src[lane + i * 32];
        if (lane == 0) {                       // reset for next graph replay
            g_best[b] = 0ULL;
            __threadfence();
            g_cnt[b] = 0;
        }
    }
}

__global__ __launch_bounds__(256, 4) void knn_persistent_kernel(
    const float* __restrict__ inputs,   // [BB, DD]
    const float* __restrict__ buffer,   // [BB, MM, DD]
    float* __restrict__ out)            // [BB, DD]
{
    const int gw   = blockIdx.x * 8 + (threadIdx.x >> 5);
    const int lane = threadIdx.x & 31;

    // Contiguous row range for this warp (perfectly balanced 27/28 rows).
    int r0 = (int)((long long)TOTAL_ROWS * gw / WARPS_TOTAL);
    int r1 = (int)((long long)TOTAL_ROWS * (gw + 1) / WARPS_TOTAL);
    if (r0 >= r1) return;

    int r = r0;
    int b = r >> 11;                    // / MM

    // Query row in registers (reloaded only on batch crossing, <=2x per warp).
    const float4* qp = reinterpret_cast<const float4*>(inputs + (size_t)b * DD);
    float4 q0 = qp[lane], q1 = qp[lane + 32], q2 = qp[lane + 64], q3 = qp[lane + 96];

    const float4* rp = reinterpret_cast<const float4*>(buffer + (size_t)r * DD);
    float4 v0 = __ldg(rp + lane),      v1 = __ldg(rp + lane + 32),
           v2 = __ldg(rp + lane + 64), v3 = __ldg(rp + lane + 96);

    float best  = -1.0f;
    int   bestm = 0;
    int   nrows = 0;

    for (;;) {
        const int  rn        = r + 1;
        const bool have_next = (rn < r1);

        // Prefetch next row while this row's FMA + shuffle chain runs.
        float4 n0, n1, n2, n3;
        if (have_next) {
            const float4* np = reinterpret_cast<const float4*>(buffer + (size_t)rn * DD);
            n0 = __ldg(np + lane);      n1 = __ldg(np + lane + 32);
            n2 = __ldg(np + lane + 64); n3 = __ldg(np + lane + 96);
        }

        float acc = 0.0f;
        {
            float dx = v0.x - q0.x, dy = v0.y - q0.y, dz = v0.z - q0.z, dw = v0.w - q0.w;
            acc = fmaf(dx, dx, acc); acc = fmaf(dy, dy, acc);
            acc = fmaf(dz, dz, acc); acc = fmaf(dw, dw, acc);
            dx = v1.x - q1.x; dy = v1.y - q1.y; dz = v1.z - q1.z; dw = v1.w - q1.w;
            acc = fmaf(dx, dx, acc); acc = fmaf(dy, dy, acc);
            acc = fmaf(dz, dz, acc); acc = fmaf(dw, dw, acc);
            dx = v2.x - q2.x; dy = v2.y - q2.y; dz = v2.z - q2.z; dw = v2.w - q2.w;
            acc = fmaf(dx, dx, acc); acc = fmaf(dy, dy, acc);
            acc = fmaf(dz, dz, acc); acc = fmaf(dw, dw, acc);
            dx = v3.x - q3.x; dy = v3.y - q3.y; dz = v3.z - q3.z; dw = v3.w - q3.w;
            acc = fmaf(dx, dx, acc); acc = fmaf(dy, dy, acc);
            acc = fmaf(dz, dz, acc); acc = fmaf(dw, dw, acc);
        }
#pragma unroll
        for (int o = 16; o > 0; o >>= 1)
            acc += __shfl_xor_sync(0xFFFFFFFFu, acc, o);

        const int m = r & (MM - 1);
        if (acc > best) { best = acc; bestm = m; }
        nrows++;

        const int bn = have_next ? (rn >> 11) : -1;
        if (bn != b) {
            flush_batch(b, best, bestm, nrows, lane, buffer, out);
            if (!have_next) break;
            b = bn;
            qp = reinterpret_cast<const float4*>(inputs + (size_t)b * DD);
            q0 = qp[lane]; q1 = qp[lane + 32]; q2 = qp[lane + 64]; q3 = qp[lane + 96];
            best = -1.0f; bestm = 0; nrows = 0;
        }
        r  = rn;
        v0 = n0; v1 = n1; v2 = n2; v3 = n3;
    }
}

extern "C" void kernel_launch(void* const* d_in, const int* in_sizes, int n_in,
                              void* d_out, int out_size)
{
    const float* inputs;
    const float* buffer;
    // inputs has BB*DD = 32768 elems, buffer has BB*MM*DD = 67108864.
    if (in_sizes[0] == BB * DD) {
        inputs = (const float*)d_in[0];
        buffer = (const float*)d_in[1];
    } else {
        inputs = (const float*)d_in[1];
        buffer = (const float*)d_in[0];
    }
    float* out = (float*)d_out;

    knn_persistent_kernel<<<GRID_BLOCKS, 256>>>(inputs, buffer, out);
}